// round 9
// baseline (speedup 1.0000x reference)
#include <cuda_runtime.h>
#include <cuda_fp16.h>
#include <math.h>
#include <float.h>
#include <stdint.h>

#define BB 4
#define NN 2048
#define DD 1024
#define RR 64
#define LN_EPS 1e-5f
#define NTOK (BB*NN)
#define ESHIFT 10.0f

// ---------------- scratch (no allocations allowed) ----------------
__device__ __half g_Qh[NTOK * RR];                    // 1 MB
__device__ __half g_Kh[NTOK * RR];                    // 1 MB
__device__ float  g_inv[NTOK];                        // 32 KB
__device__ float  g_L[NTOK];                          // 32 KB row sums of E
__device__ __half g_Ph[(size_t)BB * NN * NN];         // 32 MB E=exp(s-SHIFT) fp16
__device__ __half g_xt[(size_t)BB * DD * NN];         // 16 MB x^T fp16
__device__ __half g_xh[(size_t)BB * NN * DD];         // 16 MB x   fp16
__device__ __half g_Ut[RR * DD];                      // 128 KB U^T fp16
__device__ __half g_Vt[RR * DD];                      // 128 KB V^T fp16
__device__ float  g_delta[(size_t)BB * NN * DD];      // 32 MB

// ================= warp-mma helpers =================
__device__ __forceinline__ uint32_t smem_u32(const void* p) {
    uint32_t a;
    asm("{ .reg .u64 t; cvta.to.shared.u64 t, %1; cvt.u32.u64 %0, t; }" : "=r"(a) : "l"(p));
    return a;
}
__device__ __forceinline__ void ldsm_x4(uint32_t& r0, uint32_t& r1, uint32_t& r2,
                                        uint32_t& r3, uint32_t addr) {
    asm volatile("ldmatrix.sync.aligned.m8n8.x4.shared.b16 {%0,%1,%2,%3}, [%4];"
                 : "=r"(r0), "=r"(r1), "=r"(r2), "=r"(r3) : "r"(addr));
}
__device__ __forceinline__ void mma16816(float* c, const uint32_t* a,
                                         uint32_t b0, uint32_t b1) {
    asm volatile("mma.sync.aligned.m16n8k16.row.col.f32.f16.f16.f32 "
                 "{%0,%1,%2,%3}, {%4,%5,%6,%7}, {%8,%9}, {%0,%1,%2,%3};"
                 : "+f"(c[0]), "+f"(c[1]), "+f"(c[2]), "+f"(c[3])
                 : "r"(a[0]), "r"(a[1]), "r"(a[2]), "r"(a[3]), "r"(b0), "r"(b1));
}
__device__ __forceinline__ void cp_async16(uint32_t saddr, const void* gp) {
    size_t ga = __cvta_generic_to_global(gp);
    asm volatile("cp.async.cg.shared.global [%0], [%1], 16;" :: "r"(saddr), "l"(ga) : "memory");
}
__device__ __forceinline__ void cp_commit() {
    asm volatile("cp.async.commit_group;" ::: "memory");
}
template <int N> __device__ __forceinline__ void cp_wait() {
    asm volatile("cp.async.wait_group %0;" :: "n"(N) : "memory");
}

#define STR 72   // padded smem row stride in halves (144B -> conflict-free ldmatrix)

// ---------------- per token: inv=1/sqrt(max(sum mask,1)); zero L -------------
__global__ void reff_kernel(const float* __restrict__ mask) {
    int t = blockIdx.x * blockDim.x + threadIdx.x;
    if (t >= NTOK) return;
    const float4* m = (const float4*)(mask + (size_t)t * RR);
    float s = 0.f;
#pragma unroll
    for (int i = 0; i < RR / 4; i++) { float4 v = m[i]; s += v.x + v.y + v.z + v.w; }
    g_inv[t] = rsqrtf(fmaxf(s, 1.0f));
    g_L[t] = 0.f;
}

// ---------------- x -> xh (fp16 row-major) and xt (fp16 d-major) -------------
__global__ __launch_bounds__(256) void xt_kernel(const float* __restrict__ x) {
    __shared__ float t[32][33];
    int b = blockIdx.z, n0 = blockIdx.x * 32, d0 = blockIdx.y * 32;
    int tx = threadIdx.x & 31, ty = threadIdx.x >> 5;
    const float* xb = x + (size_t)b * NN * DD;
#pragma unroll
    for (int r = 0; r < 4; r++) {
        int i = ty + r * 8;
        float v = xb[(size_t)(n0 + i) * DD + d0 + tx];
        t[i][tx] = v;
        g_xh[(size_t)(b * NN + n0 + i) * DD + d0 + tx] = __float2half_rn(v);
    }
    __syncthreads();
    __half* xt = g_xt + (size_t)b * DD * NN;
#pragma unroll
    for (int r = 0; r < 4; r++) {
        int j = ty + r * 8;
        xt[(size_t)(d0 + j) * NN + n0 + tx] = __float2half_rn(t[tx][j]);
    }
}

// ---------------- U,V -> Ut,Vt (fp16, [R][D]) --------------------------------
__global__ __launch_bounds__(256) void wt_kernel(const float* __restrict__ U,
                                                 const float* __restrict__ V) {
    __shared__ float t[32][33];
    int d0 = blockIdx.x * 32, r0 = blockIdx.y * 32;
    const float* W = blockIdx.z ? V : U;
    __half* O = blockIdx.z ? g_Vt : g_Ut;
    int tx = threadIdx.x & 31, ty = threadIdx.x >> 5;
#pragma unroll
    for (int r = 0; r < 4; r++) {
        int i = ty + r * 8;
        t[i][tx] = W[(size_t)(d0 + i) * RR + r0 + tx];
    }
    __syncthreads();
#pragma unroll
    for (int r = 0; r < 4; r++) {
        int j = ty + r * 8;
        O[(size_t)(r0 + j) * DD + d0 + tx] = __float2half_rn(t[tx][j]);
    }
}

// ---------------- proj via HMMA: Q/K = (xh @ [Ut|Vt]^T) * mask ---------------
// block: 64 tokens x 128 cols (Q 0..63 | K 64..127), BK=64, 8 warps (2m x 4n)
#define PSTAGE_A (64 * STR)
#define PSTAGE_B (128 * STR)
#define PSTAGE   (PSTAGE_A + PSTAGE_B)
#define PSMEM_BYTES (3 * PSTAGE * 2)

__device__ __forceinline__ void proj_load_stage(uint32_t sBase, const __half* Xrow,
                                                int tid, int s, int k0) {
    uint32_t aOff = sBase + (uint32_t)(s * PSTAGE) * 2;
    uint32_t bOff = sBase + (uint32_t)(s * PSTAGE + PSTAGE_A) * 2;
#pragma unroll
    for (int i = 0; i < 2; i++) {
        int u = tid + i * 256;              // 0..511
        int row = u >> 3, col = (u & 7) * 8;
        cp_async16(aOff + (uint32_t)(row * STR + col) * 2,
                   Xrow + (size_t)row * DD + k0 + col);
    }
#pragma unroll
    for (int i = 0; i < 4; i++) {
        int u = tid + i * 256;              // 0..1023
        int row = u >> 3, col = (u & 7) * 8;
        const __half* src = (row < 64) ? (g_Ut + (size_t)row * DD + k0 + col)
                                       : (g_Vt + (size_t)(row - 64) * DD + k0 + col);
        cp_async16(bOff + (uint32_t)(row * STR + col) * 2, src);
    }
    cp_commit();
}

__global__ __launch_bounds__(256, 2) void proj_mma_kernel(const float* __restrict__ mask) {
    extern __shared__ __half psm[];
    int t0 = blockIdx.x * 64;
    int tid = threadIdx.x, wid = tid >> 5, lane = tid & 31;
    int wm = (wid & 1) * 32, wn = (wid >> 1) * 32;
    uint32_t sBase = smem_u32(psm);
    const __half* Xrow = g_xh + (size_t)t0 * DD;

    proj_load_stage(sBase, Xrow, tid, 0, 0);
    proj_load_stage(sBase, Xrow, tid, 1, 64);

    float acc[2][4][4] = {};
    for (int c = 0; c < DD / 64; c++) {
        int s = c % 3;
        if (c < DD / 64 - 1) cp_wait<1>(); else cp_wait<0>();
        __syncthreads();
        if (c + 2 < DD / 64) proj_load_stage(sBase, Xrow, tid, (c + 2) % 3, (c + 2) * 64);
        uint32_t aBase = sBase + (uint32_t)(s * PSTAGE) * 2;
        uint32_t bBase = sBase + (uint32_t)(s * PSTAGE + PSTAGE_A) * 2;
#pragma unroll
        for (int kk = 0; kk < 64; kk += 16) {
            uint32_t a[2][4];
#pragma unroll
            for (int mf = 0; mf < 2; mf++) {
                int row = wm + mf * 16 + (lane & 15);
                ldsm_x4(a[mf][0], a[mf][1], a[mf][2], a[mf][3],
                        aBase + (uint32_t)(row * STR + kk + (lane >> 4) * 8) * 2);
            }
#pragma unroll
            for (int nf = 0; nf < 2; nf++) {
                int g = lane >> 3;
                int row = wn + nf * 16 + (lane & 7) + (g >> 1) * 8;
                uint32_t b0, b1, b2, b3;
                ldsm_x4(b0, b1, b2, b3,
                        bBase + (uint32_t)(row * STR + kk + (g & 1) * 8) * 2);
#pragma unroll
                for (int mf = 0; mf < 2; mf++) {
                    mma16816(acc[mf][nf * 2],     a[mf], b0, b1);
                    mma16816(acc[mf][nf * 2 + 1], a[mf], b2, b3);
                }
            }
        }
        __syncthreads();
    }

#pragma unroll
    for (int mf = 0; mf < 2; mf++) {
#pragma unroll
        for (int rr = 0; rr < 2; rr++) {
            int token = t0 + wm + mf * 16 + lane / 4 + rr * 8;
#pragma unroll
            for (int nn = 0; nn < 4; nn++) {
                int col = wn + nn * 8 + (lane & 3) * 2;
                float v0 = acc[mf][nn][rr * 2], v1 = acc[mf][nn][rr * 2 + 1];
                int r = (col < 64) ? col : col - 64;
                float2 mm = *(const float2*)(mask + (size_t)token * RR + r);
                __half2 h = __floats2half2_rn(v0 * mm.x, v1 * mm.y);
                __half* dst = (col < 64) ? g_Qh : g_Kh;
                *(__half2*)&dst[(size_t)token * RR + r] = h;
            }
        }
    }
}

// ---- scores+exp: E[q][k] = fp16(exp(QK*inv[q] - SHIFT)); L[q] += rowsum -----
__global__ __launch_bounds__(256, 2) void scores_mma_kernel() {
    __shared__ __half As[128 * STR];
    __shared__ __half Bs[128 * STR];
    int b = blockIdx.z, q0 = blockIdx.y * 128, k0 = blockIdx.x * 128;
    int tid = threadIdx.x, wid = tid >> 5, lane = tid & 31;
    int wm = (wid & 3) * 32, wn = (wid >> 2) * 64;

#pragma unroll
    for (int i = 0; i < 4; i++) {
        int idx = tid + i * 256;
        int row = idx >> 3, col = (idx & 7) * 8;
        *(uint4*)&As[row * STR + col] =
            *(const uint4*)(g_Qh + (size_t)(b * NN + q0 + row) * RR + col);
        *(uint4*)&Bs[row * STR + col] =
            *(const uint4*)(g_Kh + (size_t)(b * NN + k0 + row) * RR + col);
    }
    __syncthreads();

    float acc[2][8][4] = {};
    uint32_t aBase = smem_u32(As), bBase = smem_u32(Bs);
#pragma unroll
    for (int kk = 0; kk < RR; kk += 16) {
        uint32_t a[2][4];
#pragma unroll
        for (int mf = 0; mf < 2; mf++) {
            int row = wm + mf * 16 + (lane & 15);
            ldsm_x4(a[mf][0], a[mf][1], a[mf][2], a[mf][3],
                    aBase + (uint32_t)(row * STR + kk + (lane >> 4) * 8) * 2);
        }
#pragma unroll
        for (int nf = 0; nf < 4; nf++) {
            int g = lane >> 3;
            int row = wn + nf * 16 + (lane & 7) + (g >> 1) * 8;
            uint32_t b0, b1, b2, b3;
            ldsm_x4(b0, b1, b2, b3,
                    bBase + (uint32_t)(row * STR + kk + (g & 1) * 8) * 2);
#pragma unroll
            for (int mf = 0; mf < 2; mf++) {
                mma16816(acc[mf][nf * 2],     a[mf], b0, b1);
                mma16816(acc[mf][nf * 2 + 1], a[mf], b2, b3);
            }
        }
    }

    __half* Pb = g_Ph + (size_t)b * NN * NN;
#pragma unroll
    for (int mf = 0; mf < 2; mf++) {
        int r0 = q0 + wm + mf * 16 + lane / 4;
        float inv0 = g_inv[b * NN + r0];
        float inv1 = g_inv[b * NN + r0 + 8];
        float sum0 = 0.f, sum1 = 0.f;
#pragma unroll
        for (int nf = 0; nf < 8; nf++) {
            int col = k0 + wn + nf * 8 + (lane & 3) * 2;
            __half2 h0 = __floats2half2_rn(__expf(acc[mf][nf][0] * inv0 - ESHIFT),
                                           __expf(acc[mf][nf][1] * inv0 - ESHIFT));
            __half2 h1 = __floats2half2_rn(__expf(acc[mf][nf][2] * inv1 - ESHIFT),
                                           __expf(acc[mf][nf][3] * inv1 - ESHIFT));
            *(__half2*)&Pb[(size_t)r0 * NN + col] = h0;
            *(__half2*)&Pb[(size_t)(r0 + 8) * NN + col] = h1;
            float2 f0 = __half22float2(h0), f1 = __half22float2(h1);
            sum0 += f0.x + f0.y;
            sum1 += f1.x + f1.y;
        }
        sum0 += __shfl_xor_sync(0xffffffffu, sum0, 1);
        sum0 += __shfl_xor_sync(0xffffffffu, sum0, 2);
        sum1 += __shfl_xor_sync(0xffffffffu, sum1, 1);
        sum1 += __shfl_xor_sync(0xffffffffu, sum1, 2);
        if ((lane & 3) == 0) {
            atomicAdd(&g_L[b * NN + r0], sum0);
            atomicAdd(&g_L[b * NN + r0 + 8], sum1);
        }
    }
}

// ------- delta = (E @ x) / L : CTA 128x128, 4 warps, warp tile 64x64 ---------
#define DSTAGE (128 * STR)
#define DSMEM_BYTES (3 * 2 * DSTAGE * 2)

__device__ __forceinline__ void delta_load_stage(
    uint32_t sBase, const __half* Pb, const __half* Xb,
    int q0, int d0, int tid, int s, int k0) {
    uint32_t aOff = sBase + (uint32_t)((s * 2) * DSTAGE) * 2;
    uint32_t bOff = sBase + (uint32_t)((s * 2 + 1) * DSTAGE) * 2;
#pragma unroll
    for (int i = 0; i < 8; i++) {       // 128 rows x 64 halves, 128 threads
        int u = tid + i * 128;
        int row = u >> 3, col = (u & 7) * 8;
        cp_async16(aOff + (uint32_t)(row * STR + col) * 2,
                   Pb + (size_t)(q0 + row) * NN + k0 + col);
        cp_async16(bOff + (uint32_t)(row * STR + col) * 2,
                   Xb + (size_t)(d0 + row) * NN + k0 + col);
    }
    cp_commit();
}

__global__ __launch_bounds__(128, 2) void delta_mma_kernel() {
    extern __shared__ __half dsm[];
    int b = blockIdx.z, q0 = blockIdx.y * 128, d0 = blockIdx.x * 128;
    const __half* Pb = g_Ph + (size_t)b * NN * NN;
    const __half* Xb = g_xt + (size_t)b * DD * NN;
    int tid = threadIdx.x, wid = tid >> 5, lane = tid & 31;
    int wm = (wid & 1) * 64, wn = (wid >> 1) * 64;
    uint32_t sBase = smem_u32(dsm);

    delta_load_stage(sBase, Pb, Xb, q0, d0, tid, 0, 0);
    delta_load_stage(sBase, Pb, Xb, q0, d0, tid, 1, 64);

    float acc[4][8][4] = {};
    for (int c = 0; c < NN / 64; c++) {
        int s = c % 3;
        if (c < NN / 64 - 1) cp_wait<1>(); else cp_wait<0>();
        __syncthreads();
        if (c + 2 < NN / 64)
            delta_load_stage(sBase, Pb, Xb, q0, d0, tid, (c + 2) % 3, (c + 2) * 64);
        uint32_t aBase = sBase + (uint32_t)((s * 2) * DSTAGE) * 2;
        uint32_t bBase = sBase + (uint32_t)((s * 2 + 1) * DSTAGE) * 2;
#pragma unroll
        for (int kk = 0; kk < 64; kk += 16) {
            uint32_t a[4][4];
#pragma unroll
            for (int mf = 0; mf < 4; mf++) {
                int row = wm + mf * 16 + (lane & 15);
                ldsm_x4(a[mf][0], a[mf][1], a[mf][2], a[mf][3],
                        aBase + (uint32_t)(row * STR + kk + (lane >> 4) * 8) * 2);
            }
#pragma unroll
            for (int nf = 0; nf < 4; nf++) {
                int g = lane >> 3;
                int row = wn + nf * 16 + (lane & 7) + (g >> 1) * 8;
                uint32_t b0, b1, b2, b3;
                ldsm_x4(b0, b1, b2, b3,
                        bBase + (uint32_t)(row * STR + kk + (g & 1) * 8) * 2);
#pragma unroll
                for (int mf = 0; mf < 4; mf++) {
                    mma16816(acc[mf][nf * 2],     a[mf], b0, b1);
                    mma16816(acc[mf][nf * 2 + 1], a[mf], b2, b3);
                }
            }
        }
    }

    float* dp = g_delta + ((size_t)b * NN + q0) * DD + d0;
#pragma unroll
    for (int mf = 0; mf < 4; mf++) {
        int row = wm + mf * 16 + lane / 4;
        float il0 = 1.0f / g_L[b * NN + q0 + row];
        float il1 = 1.0f / g_L[b * NN + q0 + row + 8];
#pragma unroll
        for (int nf = 0; nf < 8; nf++) {
            int col = wn + nf * 8 + (lane & 3) * 2;
            *(float2*)&dp[(size_t)row * DD + col] =
                make_float2(acc[mf][nf][0] * il0, acc[mf][nf][1] * il0);
            *(float2*)&dp[(size_t)(row + 8) * DD + col] =
                make_float2(acc[mf][nf][2] * il1, acc[mf][nf][3] * il1);
        }
    }
}

// ---------------- out = LN(x + delta) ----------------------------------------
__global__ __launch_bounds__(256) void ln_kernel(
    const float* __restrict__ x, const float* __restrict__ gamma,
    const float* __restrict__ beta, float* __restrict__ out) {
    __shared__ float red[8];
    size_t token = blockIdx.x;
    const float* xr = x + token * DD;
    const float* dr = g_delta + token * DD;
    int tid = threadIdx.x;
    float4 xv = *(const float4*)(xr + tid * 4);
    float4 dv = *(const float4*)(dr + tid * 4);
    float y[4] = {xv.x + dv.x, xv.y + dv.y, xv.z + dv.z, xv.w + dv.w};
    float s = y[0] + y[1] + y[2] + y[3];
#pragma unroll
    for (int o = 16; o > 0; o >>= 1) s += __shfl_xor_sync(0xffffffffu, s, o);
    if ((tid & 31) == 0) red[tid >> 5] = s;
    __syncthreads();
    if (tid < 32) {
        float t = (tid < 8) ? red[tid] : 0.f;
#pragma unroll
        for (int o = 4; o > 0; o >>= 1) t += __shfl_xor_sync(0xffffffffu, t, o);
        if (tid == 0) red[0] = t;
    }
    __syncthreads();
    float mu = red[0] * (1.0f / DD);
    __syncthreads();
    float vs = 0.f;
#pragma unroll
    for (int i = 0; i < 4; i++) { float d = y[i] - mu; vs += d * d; }
#pragma unroll
    for (int o = 16; o > 0; o >>= 1) vs += __shfl_xor_sync(0xffffffffu, vs, o);
    if ((tid & 31) == 0) red[tid >> 5] = vs;
    __syncthreads();
    if (tid < 32) {
        float t = (tid < 8) ? red[tid] : 0.f;
#pragma unroll
        for (int o = 4; o > 0; o >>= 1) t += __shfl_xor_sync(0xffffffffu, t, o);
        if (tid == 0) red[0] = t;
    }
    __syncthreads();
    float inv = rsqrtf(red[0] * (1.0f / DD) + LN_EPS);
    float4 gv = *(const float4*)(gamma + tid * 4);
    float4 bv = *(const float4*)(beta + tid * 4);
    float4 o;
    o.x = (y[0] - mu) * inv * gv.x + bv.x;
    o.y = (y[1] - mu) * inv * gv.y + bv.y;
    o.z = (y[2] - mu) * inv * gv.z + bv.z;
    o.w = (y[3] - mu) * inv * gv.w + bv.w;
    *(float4*)(out + token * DD + tid * 4) = o;
}

extern "C" void kernel_launch(void* const* d_in, const int* in_sizes, int n_in,
                              void* d_out, int out_size) {
    const float* x     = (const float*)d_in[0];
    const float* mask  = (const float*)d_in[1];
    const float* U     = (const float*)d_in[2];
    const float* Vw    = (const float*)d_in[3];
    const float* gamma = (const float*)d_in[4];
    const float* beta  = (const float*)d_in[5];
    float* out = (float*)d_out;

    static bool attr_done = false;
    if (!attr_done) {
        cudaFuncSetAttribute(delta_mma_kernel,
                             cudaFuncAttributeMaxDynamicSharedMemorySize, DSMEM_BYTES);
        cudaFuncSetAttribute(proj_mma_kernel,
                             cudaFuncAttributeMaxDynamicSharedMemorySize, PSMEM_BYTES);
        attr_done = true;
    }

    reff_kernel<<<(NTOK + 255) / 256, 256>>>(mask);
    xt_kernel<<<dim3(NN / 32, DD / 32, BB), 256>>>(x);
    wt_kernel<<<dim3(DD / 32, RR / 32, 2), 256>>>(U, Vw);
    proj_mma_kernel<<<NTOK / 64, 256, PSMEM_BYTES>>>(mask);
    scores_mma_kernel<<<dim3(NN / 128, NN / 128, BB), 256>>>();
    delta_mma_kernel<<<dim3(DD / 128, NN / 128, BB), 128, DSMEM_BYTES>>>();
    ln_kernel<<<NTOK, 256>>>(x, gamma, beta, out);
}

// round 10
// speedup vs baseline: 1.5031x; 1.5031x over previous
#include <cuda_runtime.h>
#include <cuda_fp16.h>
#include <math.h>
#include <float.h>
#include <stdint.h>

#define BB 4
#define NN 2048
#define DD 1024
#define RR 64
#define LN_EPS 1e-5f
#define NTOK (BB*NN)
#define ESHIFT 10.0f

// ---------------- scratch (no allocations allowed) ----------------
__device__ __half g_Qh[NTOK * RR];                    // 1 MB
__device__ __half g_Kh[NTOK * RR];                    // 1 MB
__device__ float  g_inv[NTOK];                        // 32 KB
__device__ float  g_L[NTOK];                          // 32 KB row sums of E
__device__ __half g_Ph[(size_t)BB * NN * NN];         // 32 MB E=exp(s-SHIFT) fp16
__device__ __half g_xt[(size_t)BB * DD * NN];         // 16 MB x^T fp16
__device__ __half g_xh[(size_t)BB * NN * DD];         // 16 MB x   fp16
__device__ __half g_Ut[RR * DD];                      // 128 KB U^T fp16
__device__ __half g_Vt[RR * DD];                      // 128 KB V^T fp16
__device__ float  g_delta[(size_t)BB * NN * DD];      // 32 MB

// ================= warp-mma helpers =================
__device__ __forceinline__ uint32_t smem_u32(const void* p) {
    uint32_t a;
    asm("{ .reg .u64 t; cvta.to.shared.u64 t, %1; cvt.u32.u64 %0, t; }" : "=r"(a) : "l"(p));
    return a;
}
__device__ __forceinline__ void ldsm_x4(uint32_t& r0, uint32_t& r1, uint32_t& r2,
                                        uint32_t& r3, uint32_t addr) {
    asm volatile("ldmatrix.sync.aligned.m8n8.x4.shared.b16 {%0,%1,%2,%3}, [%4];"
                 : "=r"(r0), "=r"(r1), "=r"(r2), "=r"(r3) : "r"(addr));
}
__device__ __forceinline__ void mma16816(float* c, const uint32_t* a,
                                         uint32_t b0, uint32_t b1) {
    asm volatile("mma.sync.aligned.m16n8k16.row.col.f32.f16.f16.f32 "
                 "{%0,%1,%2,%3}, {%4,%5,%6,%7}, {%8,%9}, {%0,%1,%2,%3};"
                 : "+f"(c[0]), "+f"(c[1]), "+f"(c[2]), "+f"(c[3])
                 : "r"(a[0]), "r"(a[1]), "r"(a[2]), "r"(a[3]), "r"(b0), "r"(b1));
}
__device__ __forceinline__ void cp_async16(uint32_t saddr, const void* gp) {
    size_t ga = __cvta_generic_to_global(gp);
    asm volatile("cp.async.cg.shared.global [%0], [%1], 16;" :: "r"(saddr), "l"(ga) : "memory");
}
__device__ __forceinline__ void cp_commit() {
    asm volatile("cp.async.commit_group;" ::: "memory");
}
template <int N> __device__ __forceinline__ void cp_wait() {
    asm volatile("cp.async.wait_group %0;" :: "n"(N) : "memory");
}

#define STR 72   // padded smem row stride in halves (144B -> conflict-free ldmatrix)

// ---------------- per token: inv=1/sqrt(max(sum mask,1)); zero L -------------
__global__ void reff_kernel(const float* __restrict__ mask) {
    int t = blockIdx.x * blockDim.x + threadIdx.x;
    if (t >= NTOK) return;
    const float4* m = (const float4*)(mask + (size_t)t * RR);
    float s = 0.f;
#pragma unroll
    for (int i = 0; i < RR / 4; i++) { float4 v = m[i]; s += v.x + v.y + v.z + v.w; }
    g_inv[t] = rsqrtf(fmaxf(s, 1.0f));
    g_L[t] = 0.f;
}

// ---------------- x -> xh (fp16 row-major) and xt (fp16 d-major) -------------
__global__ __launch_bounds__(256) void xt_kernel(const float* __restrict__ x) {
    __shared__ float t[32][33];
    int b = blockIdx.z, n0 = blockIdx.x * 32, d0 = blockIdx.y * 32;
    int tx = threadIdx.x & 31, ty = threadIdx.x >> 5;
    const float* xb = x + (size_t)b * NN * DD;
#pragma unroll
    for (int r = 0; r < 4; r++) {
        int i = ty + r * 8;
        float v = xb[(size_t)(n0 + i) * DD + d0 + tx];
        t[i][tx] = v;
        g_xh[(size_t)(b * NN + n0 + i) * DD + d0 + tx] = __float2half_rn(v);
    }
    __syncthreads();
    __half* xt = g_xt + (size_t)b * DD * NN;
#pragma unroll
    for (int r = 0; r < 4; r++) {
        int j = ty + r * 8;
        xt[(size_t)(d0 + j) * NN + n0 + tx] = __float2half_rn(t[tx][j]);
    }
}

// ---------------- U,V -> Ut,Vt (fp16, [R][D]) --------------------------------
__global__ __launch_bounds__(256) void wt_kernel(const float* __restrict__ U,
                                                 const float* __restrict__ V) {
    __shared__ float t[32][33];
    int d0 = blockIdx.x * 32, r0 = blockIdx.y * 32;
    const float* W = blockIdx.z ? V : U;
    __half* O = blockIdx.z ? g_Vt : g_Ut;
    int tx = threadIdx.x & 31, ty = threadIdx.x >> 5;
#pragma unroll
    for (int r = 0; r < 4; r++) {
        int i = ty + r * 8;
        t[i][tx] = W[(size_t)(d0 + i) * RR + r0 + tx];
    }
    __syncthreads();
#pragma unroll
    for (int r = 0; r < 4; r++) {
        int j = ty + r * 8;
        O[(size_t)(r0 + j) * DD + d0 + tx] = __float2half_rn(t[tx][j]);
    }
}

// ---------------- proj via HMMA: Q/K = (xh @ [Ut|Vt]^T) * mask ---------------
// block: 64 tokens x 128 cols (Q 0..63 | K 64..127), BK=64, 8 warps (2m x 4n)
#define PSTAGE_A (64 * STR)
#define PSTAGE_B (128 * STR)
#define PSTAGE   (PSTAGE_A + PSTAGE_B)
#define PSMEM_BYTES (3 * PSTAGE * 2)

__device__ __forceinline__ void proj_load_stage(uint32_t sBase, const __half* Xrow,
                                                int tid, int s, int k0) {
    uint32_t aOff = sBase + (uint32_t)(s * PSTAGE) * 2;
    uint32_t bOff = sBase + (uint32_t)(s * PSTAGE + PSTAGE_A) * 2;
#pragma unroll
    for (int i = 0; i < 2; i++) {
        int u = tid + i * 256;              // 0..511
        int row = u >> 3, col = (u & 7) * 8;
        cp_async16(aOff + (uint32_t)(row * STR + col) * 2,
                   Xrow + (size_t)row * DD + k0 + col);
    }
#pragma unroll
    for (int i = 0; i < 4; i++) {
        int u = tid + i * 256;              // 0..1023
        int row = u >> 3, col = (u & 7) * 8;
        const __half* src = (row < 64) ? (g_Ut + (size_t)row * DD + k0 + col)
                                       : (g_Vt + (size_t)(row - 64) * DD + k0 + col);
        cp_async16(bOff + (uint32_t)(row * STR + col) * 2, src);
    }
    cp_commit();
}

__global__ __launch_bounds__(256, 2) void proj_mma_kernel(const float* __restrict__ mask) {
    extern __shared__ __half psm[];
    int t0 = blockIdx.x * 64;
    int tid = threadIdx.x, wid = tid >> 5, lane = tid & 31;
    int wm = (wid & 1) * 32, wn = (wid >> 1) * 32;
    uint32_t sBase = smem_u32(psm);
    const __half* Xrow = g_xh + (size_t)t0 * DD;

    proj_load_stage(sBase, Xrow, tid, 0, 0);
    proj_load_stage(sBase, Xrow, tid, 1, 64);

    float acc[2][4][4] = {};
    for (int c = 0; c < DD / 64; c++) {
        int s = c % 3;
        if (c < DD / 64 - 1) cp_wait<1>(); else cp_wait<0>();
        __syncthreads();
        if (c + 2 < DD / 64) proj_load_stage(sBase, Xrow, tid, (c + 2) % 3, (c + 2) * 64);
        uint32_t aBase = sBase + (uint32_t)(s * PSTAGE) * 2;
        uint32_t bBase = sBase + (uint32_t)(s * PSTAGE + PSTAGE_A) * 2;
#pragma unroll
        for (int kk = 0; kk < 64; kk += 16) {
            uint32_t a[2][4];
#pragma unroll
            for (int mf = 0; mf < 2; mf++) {
                int row = wm + mf * 16 + (lane & 15);
                ldsm_x4(a[mf][0], a[mf][1], a[mf][2], a[mf][3],
                        aBase + (uint32_t)(row * STR + kk + (lane >> 4) * 8) * 2);
            }
#pragma unroll
            for (int nf = 0; nf < 2; nf++) {
                int g = lane >> 3;
                int row = wn + nf * 16 + (lane & 7) + (g >> 1) * 8;
                uint32_t b0, b1, b2, b3;
                ldsm_x4(b0, b1, b2, b3,
                        bBase + (uint32_t)(row * STR + kk + (g & 1) * 8) * 2);
#pragma unroll
                for (int mf = 0; mf < 2; mf++) {
                    mma16816(acc[mf][nf * 2],     a[mf], b0, b1);
                    mma16816(acc[mf][nf * 2 + 1], a[mf], b2, b3);
                }
            }
        }
        __syncthreads();
    }

#pragma unroll
    for (int mf = 0; mf < 2; mf++) {
#pragma unroll
        for (int rr = 0; rr < 2; rr++) {
            int token = t0 + wm + mf * 16 + lane / 4 + rr * 8;
#pragma unroll
            for (int nn = 0; nn < 4; nn++) {
                int col = wn + nn * 8 + (lane & 3) * 2;
                float v0 = acc[mf][nn][rr * 2], v1 = acc[mf][nn][rr * 2 + 1];
                int r = (col < 64) ? col : col - 64;
                float2 mm = *(const float2*)(mask + (size_t)token * RR + r);
                __half2 h = __floats2half2_rn(v0 * mm.x, v1 * mm.y);
                __half* dst = (col < 64) ? g_Qh : g_Kh;
                *(__half2*)&dst[(size_t)token * RR + r] = h;
            }
        }
    }
}

// ---- scores+exp: E[q][k] = fp16(exp(QK*inv[q] - SHIFT)); L[q] += rowsum -----
__global__ __launch_bounds__(256, 2) void scores_mma_kernel() {
    __shared__ __half As[128 * STR];
    __shared__ __half Bs[128 * STR];
    int b = blockIdx.z, q0 = blockIdx.y * 128, k0 = blockIdx.x * 128;
    int tid = threadIdx.x, wid = tid >> 5, lane = tid & 31;
    int wm = (wid & 3) * 32, wn = (wid >> 2) * 64;

#pragma unroll
    for (int i = 0; i < 4; i++) {
        int idx = tid + i * 256;
        int row = idx >> 3, col = (idx & 7) * 8;
        *(uint4*)&As[row * STR + col] =
            *(const uint4*)(g_Qh + (size_t)(b * NN + q0 + row) * RR + col);
        *(uint4*)&Bs[row * STR + col] =
            *(const uint4*)(g_Kh + (size_t)(b * NN + k0 + row) * RR + col);
    }
    __syncthreads();

    float acc[2][8][4] = {};
    uint32_t aBase = smem_u32(As), bBase = smem_u32(Bs);
#pragma unroll
    for (int kk = 0; kk < RR; kk += 16) {
        uint32_t a[2][4];
#pragma unroll
        for (int mf = 0; mf < 2; mf++) {
            int row = wm + mf * 16 + (lane & 15);
            ldsm_x4(a[mf][0], a[mf][1], a[mf][2], a[mf][3],
                    aBase + (uint32_t)(row * STR + kk + (lane >> 4) * 8) * 2);
        }
#pragma unroll
        for (int nf = 0; nf < 4; nf++) {
            int g = lane >> 3;
            int row = wn + nf * 16 + (lane & 7) + (g >> 1) * 8;
            uint32_t b0, b1, b2, b3;
            ldsm_x4(b0, b1, b2, b3,
                    bBase + (uint32_t)(row * STR + kk + (g & 1) * 8) * 2);
#pragma unroll
            for (int mf = 0; mf < 2; mf++) {
                mma16816(acc[mf][nf * 2],     a[mf], b0, b1);
                mma16816(acc[mf][nf * 2 + 1], a[mf], b2, b3);
            }
        }
    }

    __half* Pb = g_Ph + (size_t)b * NN * NN;
#pragma unroll
    for (int mf = 0; mf < 2; mf++) {
        int r0 = q0 + wm + mf * 16 + lane / 4;
        float inv0 = g_inv[b * NN + r0];
        float inv1 = g_inv[b * NN + r0 + 8];
        float sum0 = 0.f, sum1 = 0.f;
#pragma unroll
        for (int nf = 0; nf < 8; nf++) {
            int col = k0 + wn + nf * 8 + (lane & 3) * 2;
            __half2 h0 = __floats2half2_rn(__expf(acc[mf][nf][0] * inv0 - ESHIFT),
                                           __expf(acc[mf][nf][1] * inv0 - ESHIFT));
            __half2 h1 = __floats2half2_rn(__expf(acc[mf][nf][2] * inv1 - ESHIFT),
                                           __expf(acc[mf][nf][3] * inv1 - ESHIFT));
            *(__half2*)&Pb[(size_t)r0 * NN + col] = h0;
            *(__half2*)&Pb[(size_t)(r0 + 8) * NN + col] = h1;
            float2 f0 = __half22float2(h0), f1 = __half22float2(h1);
            sum0 += f0.x + f0.y;
            sum1 += f1.x + f1.y;
        }
        sum0 += __shfl_xor_sync(0xffffffffu, sum0, 1);
        sum0 += __shfl_xor_sync(0xffffffffu, sum0, 2);
        sum1 += __shfl_xor_sync(0xffffffffu, sum1, 1);
        sum1 += __shfl_xor_sync(0xffffffffu, sum1, 2);
        if ((lane & 3) == 0) {
            atomicAdd(&g_L[b * NN + r0], sum0);
            atomicAdd(&g_L[b * NN + r0 + 8], sum1);
        }
    }
}

// -- delta = (E @ x) / L : CTA 128x128, 8 warps (4m x 2n), warp tile 32x64 ----
// 3-stage cp.async + double-buffered register fragments across kk
#define DSTAGE (128 * STR)
#define DSMEM_BYTES (3 * 2 * DSTAGE * 2)

__device__ __forceinline__ void delta_load_stage(
    uint32_t sBase, const __half* Pb, const __half* Xb,
    int q0, int d0, int tid, int s, int k0) {
#pragma unroll
    for (int i = 0; i < 4; i++) {
        int u = tid + i * 256;
        int row = u >> 3, col = (u & 7) * 8;
        cp_async16(sBase + (uint32_t)((s * 2) * DSTAGE + row * STR + col) * 2,
                   Pb + (size_t)(q0 + row) * NN + k0 + col);
        cp_async16(sBase + (uint32_t)((s * 2 + 1) * DSTAGE + row * STR + col) * 2,
                   Xb + (size_t)(d0 + row) * NN + k0 + col);
    }
    cp_commit();
}

__device__ __forceinline__ void delta_load_frags(
    uint32_t aBase, uint32_t bBase, int wm, int wn, int lane, int kk,
    uint32_t a[2][4], uint32_t bf[4][4]) {
#pragma unroll
    for (int mf = 0; mf < 2; mf++) {
        int row = wm + mf * 16 + (lane & 15);
        ldsm_x4(a[mf][0], a[mf][1], a[mf][2], a[mf][3],
                aBase + (uint32_t)(row * STR + kk + (lane >> 4) * 8) * 2);
    }
    int g = lane >> 3;
#pragma unroll
    for (int nf = 0; nf < 4; nf++) {
        int row = wn + nf * 16 + (lane & 7) + (g >> 1) * 8;
        ldsm_x4(bf[nf][0], bf[nf][1], bf[nf][2], bf[nf][3],
                bBase + (uint32_t)(row * STR + kk + (g & 1) * 8) * 2);
    }
}

__global__ __launch_bounds__(256, 2) void delta_mma_kernel() {
    extern __shared__ __half dsm[];
    int b = blockIdx.z, q0 = blockIdx.y * 128, d0 = blockIdx.x * 128;
    const __half* Pb = g_Ph + (size_t)b * NN * NN;
    const __half* Xb = g_xt + (size_t)b * DD * NN;
    int tid = threadIdx.x, wid = tid >> 5, lane = tid & 31;
    int wm = (wid & 3) * 32, wn = (wid >> 2) * 64;
    uint32_t sBase = smem_u32(dsm);

    delta_load_stage(sBase, Pb, Xb, q0, d0, tid, 0, 0);
    delta_load_stage(sBase, Pb, Xb, q0, d0, tid, 1, 64);

    float acc[2][8][4] = {};
    uint32_t afr[2][2][4], bfr[2][4][4];
    for (int c = 0; c < NN / 64; c++) {
        int s = c % 3;
        if (c < NN / 64 - 1) cp_wait<1>(); else cp_wait<0>();
        __syncthreads();
        if (c + 2 < NN / 64)
            delta_load_stage(sBase, Pb, Xb, q0, d0, tid, (c + 2) % 3, (c + 2) * 64);
        uint32_t aBase = sBase + (uint32_t)(s * 2) * DSTAGE * 2;
        uint32_t bBase = sBase + (uint32_t)(s * 2 + 1) * DSTAGE * 2;
        delta_load_frags(aBase, bBase, wm, wn, lane, 0, afr[0], bfr[0]);
#pragma unroll
        for (int kt = 0; kt < 4; kt++) {
            int cur = kt & 1, nxt = cur ^ 1;
            if (kt < 3)
                delta_load_frags(aBase, bBase, wm, wn, lane, (kt + 1) * 16,
                                 afr[nxt], bfr[nxt]);
#pragma unroll
            for (int nf = 0; nf < 4; nf++) {
#pragma unroll
                for (int mf = 0; mf < 2; mf++) {
                    mma16816(acc[mf][nf * 2],     afr[cur][mf], bfr[cur][nf][0], bfr[cur][nf][1]);
                    mma16816(acc[mf][nf * 2 + 1], afr[cur][mf], bfr[cur][nf][2], bfr[cur][nf][3]);
                }
            }
        }
    }

    float* dp = g_delta + ((size_t)b * NN + q0) * DD + d0;
#pragma unroll
    for (int mf = 0; mf < 2; mf++) {
        int row = wm + mf * 16 + lane / 4;
        float il0 = 1.0f / g_L[b * NN + q0 + row];
        float il1 = 1.0f / g_L[b * NN + q0 + row + 8];
#pragma unroll
        for (int nf = 0; nf < 8; nf++) {
            int col = wn + nf * 8 + (lane & 3) * 2;
            *(float2*)&dp[(size_t)row * DD + col] =
                make_float2(acc[mf][nf][0] * il0, acc[mf][nf][1] * il0);
            *(float2*)&dp[(size_t)(row + 8) * DD + col] =
                make_float2(acc[mf][nf][2] * il1, acc[mf][nf][3] * il1);
        }
    }
}

// ---------------- out = LN(x + delta) ----------------------------------------
__global__ __launch_bounds__(256) void ln_kernel(
    const float* __restrict__ x, const float* __restrict__ gamma,
    const float* __restrict__ beta, float* __restrict__ out) {
    __shared__ float red[8];
    size_t token = blockIdx.x;
    const float* xr = x + token * DD;
    const float* dr = g_delta + token * DD;
    int tid = threadIdx.x;
    float4 xv = *(const float4*)(xr + tid * 4);
    float4 dv = *(const float4*)(dr + tid * 4);
    float y[4] = {xv.x + dv.x, xv.y + dv.y, xv.z + dv.z, xv.w + dv.w};
    float s = y[0] + y[1] + y[2] + y[3];
#pragma unroll
    for (int o = 16; o > 0; o >>= 1) s += __shfl_xor_sync(0xffffffffu, s, o);
    if ((tid & 31) == 0) red[tid >> 5] = s;
    __syncthreads();
    if (tid < 32) {
        float t = (tid < 8) ? red[tid] : 0.f;
#pragma unroll
        for (int o = 4; o > 0; o >>= 1) t += __shfl_xor_sync(0xffffffffu, t, o);
        if (tid == 0) red[0] = t;
    }
    __syncthreads();
    float mu = red[0] * (1.0f / DD);
    __syncthreads();
    float vs = 0.f;
#pragma unroll
    for (int i = 0; i < 4; i++) { float d = y[i] - mu; vs += d * d; }
#pragma unroll
    for (int o = 16; o > 0; o >>= 1) vs += __shfl_xor_sync(0xffffffffu, vs, o);
    if ((tid & 31) == 0) red[tid >> 5] = vs;
    __syncthreads();
    if (tid < 32) {
        float t = (tid < 8) ? red[tid] : 0.f;
#pragma unroll
        for (int o = 4; o > 0; o >>= 1) t += __shfl_xor_sync(0xffffffffu, t, o);
        if (tid == 0) red[0] = t;
    }
    __syncthreads();
    float inv = rsqrtf(red[0] * (1.0f / DD) + LN_EPS);
    float4 gv = *(const float4*)(gamma + tid * 4);
    float4 bv = *(const float4*)(beta + tid * 4);
    float4 o;
    o.x = (y[0] - mu) * inv * gv.x + bv.x;
    o.y = (y[1] - mu) * inv * gv.y + bv.y;
    o.z = (y[2] - mu) * inv * gv.z + bv.z;
    o.w = (y[3] - mu) * inv * gv.w + bv.w;
    *(float4*)(out + token * DD + tid * 4) = o;
}

extern "C" void kernel_launch(void* const* d_in, const int* in_sizes, int n_in,
                              void* d_out, int out_size) {
    const float* x     = (const float*)d_in[0];
    const float* mask  = (const float*)d_in[1];
    const float* U     = (const float*)d_in[2];
    const float* Vw    = (const float*)d_in[3];
    const float* gamma = (const float*)d_in[4];
    const float* beta  = (const float*)d_in[5];
    float* out = (float*)d_out;

    static bool attr_done = false;
    if (!attr_done) {
        cudaFuncSetAttribute(delta_mma_kernel,
                             cudaFuncAttributeMaxDynamicSharedMemorySize, DSMEM_BYTES);
        cudaFuncSetAttribute(proj_mma_kernel,
                             cudaFuncAttributeMaxDynamicSharedMemorySize, PSMEM_BYTES);
        attr_done = true;
    }

    reff_kernel<<<(NTOK + 255) / 256, 256>>>(mask);
    xt_kernel<<<dim3(NN / 32, DD / 32, BB), 256>>>(x);
    wt_kernel<<<dim3(DD / 32, RR / 32, 2), 256>>>(U, Vw);
    proj_mma_kernel<<<NTOK / 64, 256, PSMEM_BYTES>>>(mask);
    scores_mma_kernel<<<dim3(NN / 128, NN / 128, BB), 256>>>();
    delta_mma_kernel<<<dim3(DD / 128, NN / 128, BB), 256, DSMEM_BYTES>>>();
    ln_kernel<<<NTOK, 256>>>(x, gamma, beta, out);
}